// round 16
// baseline (speedup 1.0000x reference)
#include <cuda_runtime.h>
#include <math.h>

#define NCAT   1024
#define INDIM  1024
#define HDIM   2048
#define GDIM   (4 * HDIM)      // 8192
#define OUTDIM 32000
#define WOUT_K (NCAT + HDIM)   // 3072

#define SMX_CHUNKS 64
#define SMX_CHUNK  (OUTDIM / SMX_CHUNKS)  // 500

// Scratch (no allocations allowed)
__device__ float g_gates0[GDIM];
__device__ float g_gates1[GDIM];
__device__ float g_h1[HDIM];
__device__ float g_h2[HDIM];
__device__ float g_logits[OUTDIM];
__device__ float g_pmax[SMX_CHUNKS];
__device__ float g_psum[SMX_CHUNKS];
__device__ unsigned int g_cnt0 = 0;

__device__ __forceinline__ float f4dot(float4 a, float4 b) {
    return a.x * b.x + a.y * b.y + a.z * b.z + a.w * b.w;
}
__device__ __forceinline__ float warp_reduce(float acc) {
#pragma unroll
    for (int off = 16; off; off >>= 1)
        acc += __shfl_down_sync(0xffffffffu, acc, off);
    return acc;
}
__device__ __forceinline__ float fast_sigmoid(float x) {
    return 1.0f / (1.0f + __expf(-x));
}
__device__ __forceinline__ float fast_tanh(float x) {
    return 1.0f - 2.0f / (__expf(2.0f * x) + 1.0f);
}

// ---------------------------------------------------------------------------
// K1: gates0 (fused cell0, hidden behind gates1-base blocks) + gates1-base.
//   blocks [0, 512):    gates0 rows, 2 rows/warp
//   blocks [512, 1024): gates1 base = w_hh_l1 @ h0_1 + biases
__global__ void __launch_bounds__(256, 4) k1_input_matvecs(
    const float* __restrict__ cat, const float* __restrict__ inp,
    const float* __restrict__ hidden, const float* __restrict__ cell,
    const float* __restrict__ w_ih_l0, const float* __restrict__ w_hh_l0,
    const float* __restrict__ b_ih_l0, const float* __restrict__ b_hh_l0,
    const float* __restrict__ w_hh_l1,
    const float* __restrict__ b_ih_l1, const float* __restrict__ b_hh_l1,
    float* __restrict__ out_h1, float* __restrict__ out_c1)
{
    int W = (blockIdx.x * blockDim.x + threadIdx.x) >> 5;
    int lane = threadIdx.x & 31;

    if (W < GDIM / 2) {
        int r0 = 2 * W, r1 = r0 + 1;
        const float4* a0 = (const float4*)(w_ih_l0 + (size_t)r0 * 2048);
        const float4* a1 = (const float4*)(w_ih_l0 + (size_t)r1 * 2048);
        const float4* h0 = (const float4*)(w_hh_l0 + (size_t)r0 * 2048);
        const float4* h1 = (const float4*)(w_hh_l0 + (size_t)r1 * 2048);
        const float4* vc = (const float4*)cat;
        const float4* vi = (const float4*)inp;
        const float4* vh = (const float4*)hidden;
        float acc0 = 0.f, acc1 = 0.f;
#pragma unroll
        for (int i = 0; i < 8; i++) {
            float4 x = vc[lane + 32 * i];
            acc0 += f4dot(__ldcs(&a0[lane + 32 * i]), x);
            acc1 += f4dot(__ldcs(&a1[lane + 32 * i]), x);
        }
#pragma unroll
        for (int i = 0; i < 8; i++) {
            float4 x = vi[lane + 32 * i];
            acc0 += f4dot(__ldcs(&a0[256 + lane + 32 * i]), x);
            acc1 += f4dot(__ldcs(&a1[256 + lane + 32 * i]), x);
        }
#pragma unroll
        for (int i = 0; i < 16; i++) {
            float4 x = vh[lane + 32 * i];
            acc0 += f4dot(__ldcs(&h0[lane + 32 * i]), x);
            acc1 += f4dot(__ldcs(&h1[lane + 32 * i]), x);
        }
        acc0 = warp_reduce(acc0);
        acc1 = warp_reduce(acc1);
        if (lane == 0) {
            g_gates0[r0] = acc0 + b_ih_l0[r0] + b_hh_l0[r0];
            g_gates0[r1] = acc1 + b_ih_l0[r1] + b_hh_l0[r1];
        }

        // cell0 in the last gates0 block — overlaps with gates1-base blocks.
        __shared__ bool is_last;
        __syncthreads();
        if (threadIdx.x == 0) {
            __threadfence();
            unsigned int v = atomicAdd(&g_cnt0, 1u);
            is_last = (v == (GDIM / 16) - 1u);
            if (is_last) g_cnt0 = 0u;
        }
        __syncthreads();
        if (is_last) {
            for (int j = threadIdx.x; j < HDIM; j += blockDim.x) {
                float ig = fast_sigmoid(g_gates0[j]);
                float fg = fast_sigmoid(g_gates0[HDIM + j]);
                float gg = fast_tanh(g_gates0[2 * HDIM + j]);
                float og = fast_sigmoid(g_gates0[3 * HDIM + j]);
                float c_new = fg * cell[j] + ig * gg;
                float h_new = og * fast_tanh(c_new);
                g_h1[j] = h_new;
                out_h1[j] = h_new;
                out_c1[j] = c_new;
            }
        }
    } else {
        int r0 = 2 * (W - GDIM / 2), r1 = r0 + 1;
        const float4* w0 = (const float4*)(w_hh_l1 + (size_t)r0 * 2048);
        const float4* w1 = (const float4*)(w_hh_l1 + (size_t)r1 * 2048);
        const float4* vh = (const float4*)(hidden + HDIM);
        float acc0 = 0.f, acc1 = 0.f;
#pragma unroll
        for (int i = 0; i < 16; i++) {
            float4 x = vh[lane + 32 * i];
            acc0 += f4dot(__ldcs(&w0[lane + 32 * i]), x);
            acc1 += f4dot(__ldcs(&w1[lane + 32 * i]), x);
        }
        acc0 = warp_reduce(acc0);
        acc1 = warp_reduce(acc1);
        if (lane == 0) {
            g_gates1[r0] = acc0 + b_ih_l1[r0] + b_hh_l1[r0];
            g_gates1[r1] = acc1 + b_ih_l1[r1] + b_hh_l1[r1];
        }
    }
}

// ---------------------------------------------------------------------------
// K2: g_gates1 += w_ih_l1 @ h1, 2 rows/warp.  (identical to R11)
__global__ void __launch_bounds__(256, 4) k2_l1_ih(const float* __restrict__ w_ih_l1)
{
    int W = (blockIdx.x * blockDim.x + threadIdx.x) >> 5;
    int lane = threadIdx.x & 31;
    int r0 = 2 * W, r1 = r0 + 1;
    const float4* w0 = (const float4*)(w_ih_l1 + (size_t)r0 * 2048);
    const float4* w1 = (const float4*)(w_ih_l1 + (size_t)r1 * 2048);
    const float4* vh = (const float4*)g_h1;
    float acc0 = 0.f, acc1 = 0.f;
#pragma unroll
    for (int i = 0; i < 16; i++) {
        float4 x = vh[lane + 32 * i];
        acc0 += f4dot(__ldcs(&w0[lane + 32 * i]), x);
        acc1 += f4dot(__ldcs(&w1[lane + 32 * i]), x);
    }
    acc0 = warp_reduce(acc0);
    acc1 = warp_reduce(acc1);
    if (lane == 0) {
        g_gates1[r0] += acc0;
        g_gates1[r1] += acc1;
    }
}

// ---------------------------------------------------------------------------
// cell1  (identical to R11)
__global__ void lstm_cell1_kernel(const float* __restrict__ cell,
                                  float* __restrict__ out_h2,
                                  float* __restrict__ out_c2) {
    int j = blockIdx.x * blockDim.x + threadIdx.x;
    if (j >= HDIM) return;
    float ig = fast_sigmoid(g_gates1[j]);
    float fg = fast_sigmoid(g_gates1[HDIM + j]);
    float gg = fast_tanh(g_gates1[2 * HDIM + j]);
    float og = fast_sigmoid(g_gates1[3 * HDIM + j]);
    float c_new = fg * cell[HDIM + j] + ig * gg;
    float h_new = og * fast_tanh(c_new);
    g_h2[j] = h_new;
    out_h2[j] = h_new;
    out_c2[j] = c_new;
}

// ---------------------------------------------------------------------------
// K3: FULL-row logits: g_logits[r] = w_out[r,:] @ [cat|h2] + b_out[r].
// 2 rows/warp; w_out streamed fully contiguously (393 MB sequential).
__global__ void __launch_bounds__(256, 4) k3_out_full(
    const float* __restrict__ w_out, const float* __restrict__ cat,
    const float* __restrict__ b_out)
{
    int W = (blockIdx.x * blockDim.x + threadIdx.x) >> 5;
    int lane = threadIdx.x & 31;
    int r0 = 2 * W, r1 = r0 + 1;
    const float4* w0 = (const float4*)(w_out + (size_t)r0 * WOUT_K);
    const float4* w1 = (const float4*)(w_out + (size_t)r1 * WOUT_K);
    const float4* vc = (const float4*)cat;   // 256 float4
    const float4* vh = (const float4*)g_h2;  // 512 float4
    float acc0 = 0.f, acc1 = 0.f;
#pragma unroll
    for (int i = 0; i < 8; i++) {
        float4 x = vc[lane + 32 * i];
        acc0 += f4dot(__ldcs(&w0[lane + 32 * i]), x);
        acc1 += f4dot(__ldcs(&w1[lane + 32 * i]), x);
    }
#pragma unroll
    for (int i = 0; i < 16; i++) {
        float4 x = vh[lane + 32 * i];
        acc0 += f4dot(__ldcs(&w0[256 + lane + 32 * i]), x);
        acc1 += f4dot(__ldcs(&w1[256 + lane + 32 * i]), x);
    }
    acc0 = warp_reduce(acc0);
    acc1 = warp_reduce(acc1);
    if (lane == 0) {
        g_logits[r0] = acc0 + b_out[r0];
        g_logits[r1] = acc1 + b_out[r1];
    }
}

// ---------------------------------------------------------------------------
// Parallel log_softmax stage 1  (identical to R11)
__global__ void softmax_partials(void) {
    __shared__ float red[8];
    int c = blockIdx.x;
    int tid = threadIdx.x;
    int lane = tid & 31, wid = tid >> 5;
    int base = c * SMX_CHUNK;

    float m = -INFINITY;
    for (int i = tid; i < SMX_CHUNK; i += 256) m = fmaxf(m, g_logits[base + i]);
#pragma unroll
    for (int off = 16; off; off >>= 1)
        m = fmaxf(m, __shfl_xor_sync(0xffffffffu, m, off));
    if (lane == 0) red[wid] = m;
    __syncthreads();
    if (wid == 0) {
        float v = (lane < 8) ? red[lane] : -INFINITY;
#pragma unroll
        for (int off = 4; off; off >>= 1)
            v = fmaxf(v, __shfl_xor_sync(0xffffffffu, v, off));
        if (lane == 0) red[0] = v;
    }
    __syncthreads();
    m = red[0];
    __syncthreads();

    float s = 0.f;
    for (int i = tid; i < SMX_CHUNK; i += 256) s += __expf(g_logits[base + i] - m);
#pragma unroll
    for (int off = 16; off; off >>= 1)
        s += __shfl_xor_sync(0xffffffffu, s, off);
    if (lane == 0) red[wid] = s;
    __syncthreads();
    if (wid == 0) {
        float v = (lane < 8) ? red[lane] : 0.f;
#pragma unroll
        for (int off = 4; off; off >>= 1)
            v += __shfl_xor_sync(0xffffffffu, v, off);
        if (lane == 0) { g_pmax[c] = m; g_psum[c] = v; }
    }
}

// Stage 2  (identical to R11)
__global__ void softmax_finalize(float* __restrict__ out) {
    __shared__ float s_lse;
    int tid = threadIdx.x;
    if (tid < 32) {
        float m = (tid < SMX_CHUNKS) ? g_pmax[tid] : -INFINITY;
        float mm = (tid + 32 < SMX_CHUNKS) ? g_pmax[tid + 32] : -INFINITY;
        m = fmaxf(m, mm);
#pragma unroll
        for (int off = 16; off; off >>= 1)
            m = fmaxf(m, __shfl_xor_sync(0xffffffffu, m, off));
        float s = 0.f;
        if (tid < SMX_CHUNKS) s += g_psum[tid] * __expf(g_pmax[tid] - m);
        if (tid + 32 < SMX_CHUNKS) s += g_psum[tid + 32] * __expf(g_pmax[tid + 32] - m);
#pragma unroll
        for (int off = 16; off; off >>= 1)
            s += __shfl_xor_sync(0xffffffffu, s, off);
        if (tid == 0) s_lse = m + __logf(s);
    }
    __syncthreads();
    float lse = s_lse;
    int i = blockIdx.x * 256 + tid;
    if (i < OUTDIM) out[i] = g_logits[i] - lse;
}

// ---------------------------------------------------------------------------
extern "C" void kernel_launch(void* const* d_in, const int* in_sizes, int n_in,
                              void* d_out, int out_size) {
    const float* category = (const float*)d_in[0];
    const float* input    = (const float*)d_in[1];
    const float* hidden   = (const float*)d_in[2];
    const float* cell     = (const float*)d_in[3];
    const float* w_ih_l0  = (const float*)d_in[4];
    const float* w_hh_l0  = (const float*)d_in[5];
    const float* b_ih_l0  = (const float*)d_in[6];
    const float* b_hh_l0  = (const float*)d_in[7];
    const float* w_ih_l1  = (const float*)d_in[8];
    const float* w_hh_l1  = (const float*)d_in[9];
    const float* b_ih_l1  = (const float*)d_in[10];
    const float* b_hh_l1  = (const float*)d_in[11];
    const float* w_out    = (const float*)d_in[12];
    const float* b_out    = (const float*)d_in[13];

    float* out = (float*)d_out;
    float* out_logp = out;
    float* out_h1 = out + OUTDIM;
    float* out_h2 = out + OUTDIM + HDIM;
    float* out_c1 = out + OUTDIM + 2 * HDIM;
    float* out_c2 = out + OUTDIM + 3 * HDIM;

    // K1: 1024 blocks = 512 gates0 (+fused cell0) + 512 gates1-base
    k1_input_matvecs<<<1024, 256>>>(
        category, input, hidden, cell,
        w_ih_l0, w_hh_l0, b_ih_l0, b_hh_l0,
        w_hh_l1, b_ih_l1, b_hh_l1,
        out_h1, out_c1);

    // K2: 8192 rows, 2 rows/warp -> 512 blocks
    k2_l1_ih<<<GDIM / 16, 256>>>(w_ih_l1);

    // cell1
    lstm_cell1_kernel<<<HDIM / 256, 256>>>(cell, out_h2, out_c2);

    // K3: full 3072-wide rows, contiguous stream of all of w_out -> 2000 blocks
    k3_out_full<<<OUTDIM / 16, 256>>>(w_out, category, b_out);

    // parallel log_softmax: partials then finalize
    softmax_partials<<<SMX_CHUNKS, 256>>>();
    softmax_finalize<<<(OUTDIM + 255) / 256, 256>>>(out_logp);
}